// round 1
// baseline (speedup 1.0000x reference)
#include <cuda_runtime.h>

// Jump-diffusion Euler scan: 1 thread = 1 simulation path, all 500 steps in one
// kernel (paths are independent -> no cross-step sync needed).
// All inner products use packed fma.rn.f32x2 (2x fp32 FMA throughput vs FFMA).

#define BLOCK 128
#define Dd 10
#define Hh 64

#define DT_C 0.03f
#define SQRT_DT_C 0.17320508075688772f

// ---- shared-memory float offsets (each array start padded to 16B) ----
#define DW0o 0
#define DB0o 640
#define DW1o 704
#define DB1o 4800
#define DW2o 4864
#define DB2o 5504
#define JW0o 5516
#define JB0o 6156
#define JW1o 6220
#define JB1o 10316
#define JW2o 10380
#define JB2o 11020
#define MEANo 11032
#define COVo 11044
#define DIFFo 11148
#define HOFFo 11168
#define SMEM_FLOATS (HOFFo + Hh * BLOCK)
#define SMEM_BYTES (SMEM_FLOATS * 4)

typedef unsigned long long u64;

__device__ __forceinline__ u64 splat2(float a) {
    u64 r;
    asm("mov.b64 %0, {%1, %1};" : "=l"(r) : "f"(a));
    return r;
}
__device__ __forceinline__ void unpack2(u64 v, float& a, float& b) {
    asm("mov.b64 {%0, %1}, %2;" : "=f"(a), "=f"(b) : "l"(v));
}
__device__ __forceinline__ u64 ffma2(u64 a, u64 b, u64 c) {
    u64 d;
    asm("fma.rn.f32x2 %0, %1, %2, %3;" : "=l"(d) : "l"(a), "l"(b), "l"(c));
    return d;
}
__device__ __forceinline__ float leaky(float v) {
    // leaky_relu(v, 0.01) == max(v, 0.01*v) for slope in (0,1)
    return fmaxf(v, 0.01f * v);
}

// One MLP: x[10] -> 64 (leaky) -> 64 (leaky) -> 10 (linear).
// Weights in smem (broadcast LDS); hidden activations in smem column hc
// ([k][tid] layout: stride BLOCK floats, coalesced & conflict-free; each
// thread touches only its own column -> no block sync).
__device__ __forceinline__ void mlp_eval(
    const float* __restrict__ sm,
    int w0, int b0, int w1, int b1, int w2, int b2,
    const float x[Dd], float* __restrict__ hc, float out[Dd])
{
    u64 acc[Hh / 2];

    // ---- layer 1: 10 -> 64 ----
    {
        const u64* bp = (const u64*)(sm + b0);
#pragma unroll
        for (int j = 0; j < Hh / 2; j++) acc[j] = bp[j];
#pragma unroll
        for (int k = 0; k < Dd; k++) {
            u64 xs = splat2(x[k]);
            const u64* wr = (const u64*)(sm + w0 + k * Hh);
#pragma unroll
            for (int j = 0; j < Hh / 2; j++) acc[j] = ffma2(xs, wr[j], acc[j]);
        }
#pragma unroll
        for (int j = 0; j < Hh / 2; j++) {
            float a, b;
            unpack2(acc[j], a, b);
            hc[(2 * j) * BLOCK] = leaky(a);
            hc[(2 * j + 1) * BLOCK] = leaky(b);
        }
    }

    // ---- layer 2: 64 -> 64 ----
    {
        const u64* bp = (const u64*)(sm + b1);
#pragma unroll
        for (int j = 0; j < Hh / 2; j++) acc[j] = bp[j];
#pragma unroll 4
        for (int k = 0; k < Hh; k++) {
            u64 hs = splat2(hc[k * BLOCK]);
            const u64* wr = (const u64*)(sm + w1 + k * Hh);
#pragma unroll
            for (int j = 0; j < Hh / 2; j++) acc[j] = ffma2(hs, wr[j], acc[j]);
        }
#pragma unroll
        for (int j = 0; j < Hh / 2; j++) {
            float a, b;
            unpack2(acc[j], a, b);
            hc[(2 * j) * BLOCK] = leaky(a);
            hc[(2 * j + 1) * BLOCK] = leaky(b);
        }
    }

    // ---- layer 3: 64 -> 10 (linear) ----
    {
        u64 a3[Dd / 2];
        const u64* bp = (const u64*)(sm + b2);
#pragma unroll
        for (int j = 0; j < Dd / 2; j++) a3[j] = bp[j];
#pragma unroll 8
        for (int k = 0; k < Hh; k++) {
            u64 hs = splat2(hc[k * BLOCK]);
            const u64* wr = (const u64*)(sm + w2 + k * Dd);
#pragma unroll
            for (int j = 0; j < Dd / 2; j++) a3[j] = ffma2(hs, wr[j], a3[j]);
        }
#pragma unroll
        for (int j = 0; j < Dd / 2; j++) unpack2(a3[j], out[2 * j], out[2 * j + 1]);
    }
}

__global__ void __launch_bounds__(BLOCK, 1)
jump_euler_kernel(
    const float* __restrict__ z0,
    const float* __restrict__ dW0, const float* __restrict__ dB0,
    const float* __restrict__ dW1, const float* __restrict__ dB1,
    const float* __restrict__ dW2, const float* __restrict__ dB2,
    const float* __restrict__ jW0, const float* __restrict__ jB0,
    const float* __restrict__ jW1, const float* __restrict__ jB1,
    const float* __restrict__ jW2, const float* __restrict__ jB2,
    const float* __restrict__ mean_v, const float* __restrict__ covHalf,
    const float* __restrict__ diffusion,
    const float* __restrict__ pois,
    const float* __restrict__ noise_bd,
    const float* __restrict__ noise_d,
    float* __restrict__ out,
    int nsim, int steps)
{
    extern __shared__ float sm[];

    // stage weights / params into shared memory
    {
        const int tid = threadIdx.x;
        struct { int off; const float* src; int n; } cps[] = {
            {DW0o, dW0, 640}, {DB0o, dB0, 64}, {DW1o, dW1, 4096}, {DB1o, dB1, 64},
            {DW2o, dW2, 640}, {DB2o, dB2, 10},
            {JW0o, jW0, 640}, {JB0o, jB0, 64}, {JW1o, jW1, 4096}, {JB1o, jB1, 64},
            {JW2o, jW2, 640}, {JB2o, jB2, 10},
            {MEANo, mean_v, 10}, {COVo, covHalf, 100}, {DIFFo, diffusion, 20},
        };
#pragma unroll
        for (int a = 0; a < 15; a++)
            for (int i = tid; i < cps[a].n; i += BLOCK)
                sm[cps[a].off + i] = cps[a].src[i];
    }
    __syncthreads();

    const int sim = blockIdx.x * BLOCK + threadIdx.x;
    if (sim >= nsim) return;

    float* hc = sm + HOFFo + threadIdx.x;

    // load initial state and emit path[sim][0]
    float x[Dd];
    {
        const float2* zp = (const float2*)z0;
#pragma unroll
        for (int i = 0; i < Dd / 2; i++) {
            float2 v = zp[sim * (Dd / 2) + i];
            x[2 * i] = v.x;
            x[2 * i + 1] = v.y;
        }
        float2* op = (float2*)out;
        long orow = (long)sim * (steps + 1) * (Dd / 2);
#pragma unroll
        for (int i = 0; i < Dd / 2; i++)
            op[orow + i] = make_float2(x[2 * i], x[2 * i + 1]);
    }

    for (int t = 0; t < steps; t++) {
        const long base = (long)t * nsim + sim;

        const float p = pois[base];
        const float2 nb = ((const float2*)noise_bd)[base];
        float nd[Dd];
        {
            const float2* q = (const float2*)noise_d;
#pragma unroll
            for (int i = 0; i < Dd / 2; i++) {
                float2 v = q[base * (Dd / 2) + i];
                nd[2 * i] = v.x;
                nd[2 * i + 1] = v.y;
            }
        }

        float dout[Dd], jout[Dd];
        mlp_eval(sm, DW0o, DB0o, DW1o, DB1o, DW2o, DB2o, x, hc, dout);
        mlp_eval(sm, JW0o, JB0o, JW1o, JB1o, JW2o, JB2o, x, hc, jout);

        // nd @ covHalf  (10x10)
        u64 cacc[Dd / 2];
#pragma unroll
        for (int j = 0; j < Dd / 2; j++) cacc[j] = 0ull;
#pragma unroll
        for (int k = 0; k < Dd; k++) {
            u64 s = splat2(nd[k]);
            const u64* wr = (const u64*)(sm + COVo + k * Dd);
#pragma unroll
            for (int j = 0; j < Dd / 2; j++) cacc[j] = ffma2(s, wr[j], cacc[j]);
        }

        // nbd @ diffusion  (2x10)
        u64 dacc[Dd / 2];
        {
            u64 s0 = splat2(nb.x), s1 = splat2(nb.y);
            const u64* r0 = (const u64*)(sm + DIFFo);
            const u64* r1 = (const u64*)(sm + DIFFo + Dd);
#pragma unroll
            for (int j = 0; j < Dd / 2; j++) {
                dacc[j] = ffma2(s1, r1[j], ffma2(s0, r0[j], 0ull));
            }
        }

        // jump_amp = p*mean + sqrt(p) * (nd@covHalf)
        const float sp = sqrtf(p);
        const u64 ps = splat2(p), sps = splat2(sp);
        const u64* mp = (const u64*)(sm + MEANo);
        float ja[Dd], df[Dd];
#pragma unroll
        for (int j = 0; j < Dd / 2; j++) {
            u64 jv = ffma2(sps, cacc[j], ffma2(ps, mp[j], 0ull));
            unpack2(jv, ja[2 * j], ja[2 * j + 1]);
            unpack2(dacc[j], df[2 * j], df[2 * j + 1]);
        }

        // state update + store path[sim][t+1]
        float2* op = (float2*)out;
        const long orow = ((long)sim * (steps + 1) + (t + 1)) * (Dd / 2);
#pragma unroll
        for (int i = 0; i < Dd; i++) {
            x[i] = x[i] + DT_C * dout[i] + SQRT_DT_C * df[i] + ja[i] * jout[i];
        }
#pragma unroll
        for (int i = 0; i < Dd / 2; i++)
            op[orow + i] = make_float2(x[2 * i], x[2 * i + 1]);
    }
}

extern "C" void kernel_launch(void* const* d_in, const int* in_sizes, int n_in,
                              void* d_out, int out_size)
{
    const int nsim = in_sizes[0] / Dd;         // z0 is [nsim, 10]
    const int steps = in_sizes[16] / nsim;     // pois is [steps, nsim, 1]

    cudaFuncSetAttribute(jump_euler_kernel,
                         cudaFuncAttributeMaxDynamicSharedMemorySize, SMEM_BYTES);

    dim3 grid((nsim + BLOCK - 1) / BLOCK);
    jump_euler_kernel<<<grid, BLOCK, SMEM_BYTES>>>(
        (const float*)d_in[0],
        (const float*)d_in[1], (const float*)d_in[2],
        (const float*)d_in[3], (const float*)d_in[4],
        (const float*)d_in[5], (const float*)d_in[6],
        (const float*)d_in[7], (const float*)d_in[8],
        (const float*)d_in[9], (const float*)d_in[10],
        (const float*)d_in[11], (const float*)d_in[12],
        (const float*)d_in[13], (const float*)d_in[14],
        (const float*)d_in[15],
        (const float*)d_in[16], (const float*)d_in[17], (const float*)d_in[18],
        (float*)d_out, nsim, steps);
}

// round 3
// speedup vs baseline: 1.2191x; 1.2191x over previous
#include <cuda_runtime.h>

// Jump-diffusion Euler scan, S=4 thread-split per path.
// 4 threads (adjacent lanes, same warp) cooperate on one path:
//   slot s owns hidden-neuron pairs p = 4j+s (neurons 2p, 2p+1) in layers 1,2.
//   Layer-3 is k-split per slot, reduced via shfl.bfly + add.f32x2.
// Hidden activations exchanged via pre-splatted u64 smem [k][path] (syncwarp only).
// All inner products use packed fma.rn.f32x2.

#define SLOTS 4
#define PPB   112                 // paths per block
#define BLOCK (PPB * SLOTS)       // 448 threads = 14 warps
#define Dd 10
#define Hh 64

#define DT_C 0.03f
#define SQRT_DT_C 0.17320508075688772f

// ---- shared-memory float offsets ----
#define DW0o 0
#define DB0o 640
#define DW1o 704
#define DB1o 4800
#define DW2o 4864
#define DB2o 5504
#define JW0o 5516
#define JB0o 6156
#define JW1o 6220
#define JB1o 10316
#define JW2o 10380
#define JB2o 11020
#define MEANo 11032
#define COVo 11044
#define DIFFo 11148
#define HOFFo 11168               // even -> 8B aligned
#define HCS 116                   // hc row stride in u64 (112 + 4 pad: 8-bank row shift)
#define SMEM_FLOATS (HOFFo + Hh * HCS * 2)
#define SMEM_BYTES (SMEM_FLOATS * 4)

typedef unsigned long long u64;

__device__ __forceinline__ u64 splat2(float a) {
    u64 r;
    asm("mov.b64 %0, {%1, %1};" : "=l"(r) : "f"(a));
    return r;
}
__device__ __forceinline__ void unpack2(u64 v, float& a, float& b) {
    asm("mov.b64 {%0, %1}, %2;" : "=f"(a), "=f"(b) : "l"(v));
}
__device__ __forceinline__ u64 ffma2(u64 a, u64 b, u64 c) {
    u64 d;
    asm("fma.rn.f32x2 %0, %1, %2, %3;" : "=l"(d) : "l"(a), "l"(b), "l"(c));
    return d;
}
__device__ __forceinline__ u64 addf2(u64 a, u64 b) {
    u64 d;
    asm("add.rn.f32x2 %0, %1, %2;" : "=l"(d) : "l"(a), "l"(b));
    return d;
}
__device__ __forceinline__ float leaky(float v) {
    return fmaxf(v, 0.01f * v);
}

// One MLP with S=4 cooperation. xs = pre-splatted state (u64[10]).
// out[10] fully produced on every slot (replicated after reduction).
__device__ __forceinline__ void mlp_eval4(
    const float* __restrict__ sm, u64* __restrict__ hcu,
    int w0, int b0, int w1, int b1, int w2, int b2,
    const u64 xs[Dd], int g, int s, float out[Dd])
{
    u64 acc[8];

    // ---- layer 1: 10 -> 64, slot computes pairs p = 4j+s ----
    {
        const u64* bp = (const u64*)(sm + b0);
#pragma unroll
        for (int j = 0; j < 8; j++) acc[j] = bp[4 * j + s];
#pragma unroll
        for (int in = 0; in < Dd; in++) {
            const u64* wr = (const u64*)(sm + w0 + in * Hh);
#pragma unroll
            for (int j = 0; j < 8; j++) acc[j] = ffma2(xs[in], wr[4 * j + s], acc[j]);
        }
#pragma unroll
        for (int j = 0; j < 8; j++) {
            float a, b;
            unpack2(acc[j], a, b);
            int r = 8 * j + 2 * s;
            hcu[(r) * HCS + g] = splat2(leaky(a));
            hcu[(r + 1) * HCS + g] = splat2(leaky(b));
        }
    }
    __syncwarp();

    // ---- layer 2: 64 -> 64 ----
    {
        const u64* bp = (const u64*)(sm + b1);
#pragma unroll
        for (int j = 0; j < 8; j++) acc[j] = bp[4 * j + s];
#pragma unroll 8
        for (int k = 0; k < Hh; k++) {
            u64 hs = hcu[k * HCS + g];
            const u64* wr = (const u64*)(sm + w1 + k * Hh);
#pragma unroll
            for (int j = 0; j < 8; j++) acc[j] = ffma2(hs, wr[4 * j + s], acc[j]);
        }
    }
    __syncwarp();   // hc free for reuse by next MLP

    // ---- layer 3: 64 -> 10, k-split across slots, shuffle-reduce ----
    {
        float h2[16];
#pragma unroll
        for (int j = 0; j < 8; j++) {
            float a, b;
            unpack2(acc[j], a, b);
            h2[2 * j] = leaky(a);
            h2[2 * j + 1] = leaky(b);
        }
        u64 part[5];
#pragma unroll
        for (int j2 = 0; j2 < 5; j2++) part[j2] = 0ull;
#pragma unroll
        for (int jj = 0; jj < 16; jj++) {
            int k = 8 * (jj >> 1) + 2 * s + (jj & 1);   // this slot's neuron index
            u64 hv = splat2(h2[jj]);
            const u64* wr = (const u64*)(sm + w2 + k * Dd);
#pragma unroll
            for (int j2 = 0; j2 < 5; j2++) part[j2] = ffma2(hv, wr[j2], part[j2]);
        }
        const u64* b2p = (const u64*)(sm + b2);
#pragma unroll
        for (int j2 = 0; j2 < 5; j2++) {
            part[j2] = addf2(part[j2], __shfl_xor_sync(0xffffffffu, part[j2], 1));
            part[j2] = addf2(part[j2], __shfl_xor_sync(0xffffffffu, part[j2], 2));
            u64 o = addf2(part[j2], b2p[j2]);
            unpack2(o, out[2 * j2], out[2 * j2 + 1]);
        }
    }
}

__global__ void __launch_bounds__(BLOCK, 1)
jump_euler_kernel(
    const float* __restrict__ z0,
    const float* __restrict__ dW0, const float* __restrict__ dB0,
    const float* __restrict__ dW1, const float* __restrict__ dB1,
    const float* __restrict__ dW2, const float* __restrict__ dB2,
    const float* __restrict__ jW0, const float* __restrict__ jB0,
    const float* __restrict__ jW1, const float* __restrict__ jB1,
    const float* __restrict__ jW2, const float* __restrict__ jB2,
    const float* __restrict__ mean_v, const float* __restrict__ covHalf,
    const float* __restrict__ diffusion,
    const float* __restrict__ pois,
    const float* __restrict__ noise_bd,
    const float* __restrict__ noise_d,
    float* __restrict__ out,
    int nsim, int steps)
{
    extern __shared__ float sm[];

    // stage weights / params into shared memory
    {
        const int tid = threadIdx.x;
        struct { int off; const float* src; int n; } cps[] = {
            {DW0o, dW0, 640}, {DB0o, dB0, 64}, {DW1o, dW1, 4096}, {DB1o, dB1, 64},
            {DW2o, dW2, 640}, {DB2o, dB2, 10},
            {JW0o, jW0, 640}, {JB0o, jB0, 64}, {JW1o, jW1, 4096}, {JB1o, jB1, 64},
            {JW2o, jW2, 640}, {JB2o, jB2, 10},
            {MEANo, mean_v, 10}, {COVo, covHalf, 100}, {DIFFo, diffusion, 20},
        };
#pragma unroll
        for (int a = 0; a < 15; a++)
            for (int i = tid; i < cps[a].n; i += BLOCK)
                sm[cps[a].off + i] = cps[a].src[i];
    }
    __syncthreads();

    const int g = threadIdx.x >> 2;        // path within block (0..111)
    const int s = threadIdx.x & 3;         // slot
    const int path = blockIdx.x * PPB + g; // global path
    const bool valid = path < nsim;
    const int pg = valid ? path : (nsim - 1);   // clamped for safe loads

    u64* hcu = (u64*)(sm + HOFFo);

    // load initial state; emit path[pg][0]
    float x[Dd];
    u64 xs[Dd];
    {
        const float2* zp = (const float2*)z0;
#pragma unroll
        for (int i = 0; i < Dd / 2; i++) {
            float2 v = zp[(long)pg * (Dd / 2) + i];
            x[2 * i] = v.x;
            x[2 * i + 1] = v.y;
        }
#pragma unroll
        for (int i = 0; i < Dd; i++) xs[i] = splat2(x[i]);
        if (valid) {
            float2* op = (float2*)out;
            long orow = (long)path * (steps + 1) * (Dd / 2);
            op[orow + s] = make_float2(x[2 * s], x[2 * s + 1]);
            if (s == 3) op[orow + 4] = make_float2(x[8], x[9]);
        }
    }

    for (int t = 0; t < steps; t++) {
        const long base = (long)t * nsim + pg;

        const float p = pois[base];
        const float2 nb = ((const float2*)noise_bd)[base];
        float nd[Dd];
        {
            const float2* q = (const float2*)noise_d;
#pragma unroll
            for (int i = 0; i < Dd / 2; i++) {
                float2 v = q[base * (Dd / 2) + i];
                nd[2 * i] = v.x;
                nd[2 * i + 1] = v.y;
            }
        }

        float dout[Dd], jout[Dd];
        mlp_eval4(sm, hcu, DW0o, DB0o, DW1o, DB1o, DW2o, DB2o, xs, g, s, dout);
        mlp_eval4(sm, hcu, JW0o, JB0o, JW1o, JB1o, JW2o, JB2o, xs, g, s, jout);

        // nd @ covHalf  (10x10)  (replicated per slot; small)
        u64 cacc[Dd / 2];
#pragma unroll
        for (int j = 0; j < Dd / 2; j++) cacc[j] = 0ull;
#pragma unroll
        for (int k = 0; k < Dd; k++) {
            u64 sv = splat2(nd[k]);
            const u64* wr = (const u64*)(sm + COVo + k * Dd);
#pragma unroll
            for (int j = 0; j < Dd / 2; j++) cacc[j] = ffma2(sv, wr[j], cacc[j]);
        }

        // nbd @ diffusion  (2x10)
        u64 dacc[Dd / 2];
        {
            u64 s0 = splat2(nb.x), s1 = splat2(nb.y);
            const u64* r0 = (const u64*)(sm + DIFFo);
            const u64* r1 = (const u64*)(sm + DIFFo + Dd);
#pragma unroll
            for (int j = 0; j < Dd / 2; j++)
                dacc[j] = ffma2(s1, r1[j], ffma2(s0, r0[j], 0ull));
        }

        // jump_amp = p*mean + sqrt(p) * (nd@covHalf)
        const float sp = sqrtf(p);
        const u64 ps = splat2(p), sps = splat2(sp);
        const u64* mp = (const u64*)(sm + MEANo);
        float ja[Dd], df[Dd];
#pragma unroll
        for (int j = 0; j < Dd / 2; j++) {
            u64 jv = ffma2(sps, cacc[j], ffma2(ps, mp[j], 0ull));
            unpack2(jv, ja[2 * j], ja[2 * j + 1]);
            unpack2(dacc[j], df[2 * j], df[2 * j + 1]);
        }

        // state update + store path[path][t+1]
#pragma unroll
        for (int i = 0; i < Dd; i++) {
            x[i] = x[i] + DT_C * dout[i] + SQRT_DT_C * df[i] + ja[i] * jout[i];
            xs[i] = splat2(x[i]);
        }
        if (valid) {
            float2* op = (float2*)out;
            const long orow = ((long)path * (steps + 1) + (t + 1)) * (Dd / 2);
            op[orow + s] = make_float2(x[2 * s], x[2 * s + 1]);
            if (s == 3) op[orow + 4] = make_float2(x[8], x[9]);
        }
    }
}

extern "C" void kernel_launch(void* const* d_in, const int* in_sizes, int n_in,
                              void* d_out, int out_size)
{
    const int nsim = in_sizes[0] / Dd;         // z0 is [nsim, 10]
    const int steps = in_sizes[16] / nsim;     // pois is [steps, nsim, 1]

    cudaFuncSetAttribute(jump_euler_kernel,
                         cudaFuncAttributeMaxDynamicSharedMemorySize, SMEM_BYTES);

    dim3 grid((nsim + PPB - 1) / PPB);
    jump_euler_kernel<<<grid, BLOCK, SMEM_BYTES>>>(
        (const float*)d_in[0],
        (const float*)d_in[1], (const float*)d_in[2],
        (const float*)d_in[3], (const float*)d_in[4],
        (const float*)d_in[5], (const float*)d_in[6],
        (const float*)d_in[7], (const float*)d_in[8],
        (const float*)d_in[9], (const float*)d_in[10],
        (const float*)d_in[11], (const float*)d_in[12],
        (const float*)d_in[13], (const float*)d_in[14],
        (const float*)d_in[15],
        (const float*)d_in[16], (const float*)d_in[17], (const float*)d_in[18],
        (float*)d_out, nsim, steps);
}